// round 10
// baseline (speedup 1.0000x reference)
#include <cuda_runtime.h>
#include <math.h>

#define NG   512
#define IMGW 224
#define VPIX (IMGW*IMGW)
#define NPIX (3*VPIX)

// Scratch (no cudaMalloc allowed)
__device__ float  g_par[3*NG*8];     // per view, per gaussian: px,py,a,2b,c,w0,0,0
__device__ float  g_d[NPIX];         // splat output (read-only in fill)
__device__ float  g_t[NPIX];         // fill output (final pre-norm)
__device__ double g_acc[2];          // sum, sumsq

// ---------------------------------------------------------------------------
// prep: one kernel. 48 blocks x 32 threads, thread -> (view, gaussian).
// Each block (1 warp) redundantly computes global position min/max, then each
// thread applies the iterated cov chain (v+1 times, f32) + f64 3x3 inverse.
// ---------------------------------------------------------------------------
__global__ __launch_bounds__(32) void prep_kernel(const float* __restrict__ pos,
                                                  const float* __restrict__ cov,
                                                  const float* __restrict__ opa,
                                                  const float* __restrict__ imp)
{
    const int lane = threadIdx.x;
    const int bx   = blockIdx.x;          // [0,48)
    const int v    = bx >> 4;             // uniform per block
    const int n    = (bx & 15) * 32 + lane;

    if (bx == 0 && lane == 0) { g_acc[0] = 0.0; g_acc[1] = 0.0; }

    // global min/max of each coordinate over the 512 gaussians (warp-redundant)
    float mn0 =  1e30f, mn1 =  1e30f, mn2 =  1e30f;
    float mx0 = -1e30f, mx1 = -1e30f, mx2 = -1e30f;
    for (int g = lane; g < NG; g += 32) {
        float p0 = pos[g*3+0], p1 = pos[g*3+1], p2 = pos[g*3+2];
        mn0 = fminf(mn0, p0); mx0 = fmaxf(mx0, p0);
        mn1 = fminf(mn1, p1); mx1 = fmaxf(mx1, p1);
        mn2 = fminf(mn2, p2); mx2 = fmaxf(mx2, p2);
    }
    #pragma unroll
    for (int o = 16; o > 0; o >>= 1) {
        mn0 = fminf(mn0, __shfl_xor_sync(0xffffffffu, mn0, o));
        mx0 = fmaxf(mx0, __shfl_xor_sync(0xffffffffu, mx0, o));
        mn1 = fminf(mn1, __shfl_xor_sync(0xffffffffu, mn1, o));
        mx1 = fmaxf(mx1, __shfl_xor_sync(0xffffffffu, mx1, o));
        mn2 = fminf(mn2, __shfl_xor_sync(0xffffffffu, mn2, o));
        mx2 = fmaxf(mx2, __shfl_xor_sync(0xffffffffu, mx2, o));
    }
    float bmn[3] = { mn0, mn1, mn2 };
    float bmx[3] = { mx0, mx1, mx2 };

    // cov chain applied (v+1) times (fp32, matching reference ops/order)
    float C00 = cov[n*9+0], C01 = cov[n*9+1], C02 = cov[n*9+2];
    float C10 = cov[n*9+3], C11 = cov[n*9+4], C12 = cov[n*9+5];
    float C20 = cov[n*9+6], C21 = cov[n*9+7], C22 = cov[n*9+8];
    for (int it = 0; it <= v; it++) {
        float t;
        t = 0.5f*(C01 + C10); C01 = t; C10 = t;
        t = 0.5f*(C02 + C20); C02 = t; C20 = t;
        t = 0.5f*(C12 + C21); C12 = t; C21 = t;
        C00 += 1e-6f; C11 += 1e-6f; C22 += 1e-6f;
        float nrm = sqrtf(C00*C00 + C01*C01 + C02*C02 +
                          C10*C10 + C11*C11 + C12*C12 +
                          C20*C20 + C21*C21 + C22*C22);
        float den = nrm + 1e-6f;
        C00 /= den; C01 /= den; C02 /= den;
        C10 /= den; C11 /= den; C12 /= den;
        C20 /= den; C21 /= den; C22 /= den;
    }

    // f64 symmetric 3x3 inverse
    double d00 = C00, d01 = C01, d02 = C02, d11 = C11, d12 = C12, d22 = C22;
    double m00 = d11*d22 - d12*d12;
    double m01 = d02*d12 - d01*d22;
    double m02 = d01*d12 - d02*d11;
    double m11 = d00*d22 - d02*d02;
    double m12 = d01*d02 - d00*d12;
    double m22 = d00*d11 - d01*d01;
    double det = d00*m00 + d01*m01 + d02*m02;
    double idet = 1.0 / det;

    const int A0[3] = {0, 0, 2};
    const int A1[3] = {1, 2, 1};
    const int a0 = A0[v], a1 = A1[v];
    double cof[3][3] = {{m00,m01,m02},{m01,m11,m12},{m02,m12,m22}};
    float a  = (float)(cof[a0][a0]*idet) + 1e-10f;
    float b2 = 2.0f * (float)(cof[a0][a1]*idet);
    float c  = (float)(cof[a1][a1]*idet) + 1e-10f;

    // affine map to [0,111] screen coords (replicating reference fp ops)
    float mnx = bmn[a0], mxx = bmx[a0];
    float mny = bmn[a1], mxy = bmx[a1];
    float rx  = (mxx - mnx) + 1e-6f;
    float m2x = mnx - 0.5f*rx;
    float x2x = mxx + 0.5f*rx;
    float r2x = (x2x - m2x) + 1e-6f;
    float ry  = (mxy - mny) + 1e-6f;
    float m2y = mny - 0.5f*ry;
    float x2y = mxy + 0.5f*ry;
    float r2y = (x2y - m2y) + 1e-6f;
    float Pa  = pos[n*3 + a0];
    float Pb  = pos[n*3 + a1];
    float px = fminf(fmaxf((Pa - m2x) / r2x * 111.0f, 0.0f), 111.0f);
    float py = fminf(fmaxf((Pb - m2y) / r2y * 111.0f, 0.0f), 111.0f);

    float w0 = opa[n] * fminf(fmaxf(imp[n], 0.5f), 2.0f);

    float* dst = &g_par[(v*NG + n)*8];
    dst[0] = px; dst[1] = py; dst[2] = a; dst[3] = b2;
    dst[4] = c;  dst[5] = w0; dst[6] = 0.0f; dst[7] = 0.0f;
}

// ---------------------------------------------------------------------------
// Splat: 16x16 pixel tile, 128 threads, 2 pixels per thread (rows y, y+8).
// Two-sided compaction (full-cover front / partial back) + warp-uniform
// early-out in the partial loop.
// ---------------------------------------------------------------------------
__global__ __launch_bounds__(128) void splat_kernel()
{
    const int v   = blockIdx.z;
    const int fx0 = blockIdx.x * 16, fy0 = blockIdx.y * 16;
    const int t   = threadIdx.x;
    const int lane = t & 31, wid = t >> 5;
    const int fx  = fx0 + (t & 15);
    const int fyA = fy0 + (t >> 4);
    const int fyB = fyA + 8;

    float sx, vx;
    if (fx == 0)        { sx = 0.0f;   vx = 0.0f; }
    else if (fx == 223) { sx = 111.0f; vx = 0.0f; }
    else                { sx = (float)fx * 0.5f - 0.25f; vx = 0.1875f; }
    float syA, vyA;
    if (fyA == 0)        { syA = 0.0f;   vyA = 0.0f; }
    else                 { syA = (float)fyA * 0.5f - 0.25f; vyA = 0.1875f; }
    float syB, vyB;
    if (fyB == 223)      { syB = 111.0f; vyB = 0.0f; }
    else                 { syB = (float)fyB * 0.5f - 0.25f; vyB = 0.1875f; }

    const float hx  = (float)(fx  >> 1);
    const float hyA = (float)(fyA >> 1);
    const float hyB = (float)(fyB >> 1);

    // tile rect in half-res coords
    const float rx0 = (float)(fx0 >> 1), rx1 = (float)((fx0 + 15) >> 1);
    const float ry0 = (float)(fy0 >> 1), ry1 = (float)((fy0 + 15) >> 1);

    __shared__ float sp[NG * 8];
    __shared__ int   cF[4], cP[4];
    __shared__ int   s_front, s_back;
    if (t == 0) { s_front = 0; s_back = NG; }
    __syncthreads();

    const float* par = g_par + v * NG * 8;
    const unsigned ltm = (1u << lane) - 1u;

    for (int base = 0; base < NG; base += 128) {
        const int n = base + t;
        float2 p = *(const float2*)(par + n*8);
        float nx = fminf(fmaxf(p.x, rx0), rx1) - p.x;
        float ny = fminf(fmaxf(p.y, ry0), ry1) - p.y;
        bool keep = nx*nx + ny*ny < 400.0f;
        float fxd = fmaxf(p.x - rx0, rx1 - p.x);   // dist to farthest x-edge
        float fyd = fmaxf(p.y - ry0, ry1 - p.y);
        bool full  = keep && (fxd*fxd + fyd*fyd < 400.0f);
        bool partl = keep && !full;
        unsigned mF = __ballot_sync(0xffffffffu, full);
        unsigned mP = __ballot_sync(0xffffffffu, partl);
        if (lane == 0) { cF[wid] = __popc(mF); cP[wid] = __popc(mP); }
        __syncthreads();
        int offF = s_front, offP = 0, totF = 0, totP = 0;
        #pragma unroll
        for (int w = 0; w < 4; w++) {
            if (w < wid) { offF += cF[w]; offP += cP[w]; }
            totF += cF[w]; totP += cP[w];
        }
        int basePslot = s_back - totP;
        if (full | partl) {
            int slot = full ? (offF + __popc(mF & ltm))
                            : (basePslot + offP + __popc(mP & ltm));
            float4 q0 = *(const float4*)(par + n*8);
            float4 q1 = *(const float4*)(par + n*8 + 4);
            *(float4*)(sp + slot*8)     = q0;
            *(float4*)(sp + slot*8 + 4) = q1;
        }
        __syncthreads();
        if (t == 0) { s_front += totF; s_back -= totP; }
        __syncthreads();
    }
    const int nfull = s_front, pstart = s_back;

    float SA = 0.0f, mxA = -1e30f, mnA = 1e30f;
    float SB = 0.0f, mxB = -1e30f, mnB = 1e30f;
    bool skipped = false;

    // full-cover list: no mask test
    #pragma unroll 2
    for (int i = 0; i < nfull; i++) {
        float4 q0 = *(const float4*)(sp + i*8);      // px,py,a,2b
        float2 q1 = *(const float2*)(sp + i*8 + 4);  // c,w0
        float dx  = sx - q0.x;
        float dyA = syA - q0.y;
        float eA  = -(q0.z*(dx*dx + vx) + q0.w*(dx*dyA) + q1.x*(dyA*dyA + vyA));
        eA = fminf(fmaxf(eA, -20.0f), 0.0f);
        float wA = q1.y * __expf(eA);
        SA += wA; mxA = fmaxf(mxA, wA); mnA = fminf(mnA, wA);
        float dyB = syB - q0.y;
        float eB  = -(q0.z*(dx*dx + vx) + q0.w*(dx*dyB) + q1.x*(dyB*dyB + vyB));
        eB = fminf(fmaxf(eB, -20.0f), 0.0f);
        float wB = q1.y * __expf(eB);
        SB += wB; mxB = fmaxf(mxB, wB); mnB = fminf(mnB, wB);
    }
    // partial list: per-pixel half-res disc test + warp-uniform early-out
    for (int i = pstart; i < NG; i++) {
        float4 q0 = *(const float4*)(sp + i*8);
        float dxh  = hx - q0.x;
        float dxh2 = dxh * dxh;
        float dyhA = hyA - q0.y;
        float dyhB = hyB - q0.y;
        bool mA = dyhA*dyhA + dxh2 < 400.0f;
        bool mB = dyhB*dyhB + dxh2 < 400.0f;
        if (!__any_sync(0xffffffffu, mA | mB)) { skipped = true; continue; }
        float2 q1 = *(const float2*)(sp + i*8 + 4);
        float dx  = sx - q0.x;
        float wA = 0.0f, wB = 0.0f;
        if (mA) {
            float dyA = syA - q0.y;
            float eA  = -(q0.z*(dx*dx + vx) + q0.w*(dx*dyA) + q1.x*(dyA*dyA + vyA));
            eA = fminf(fmaxf(eA, -20.0f), 0.0f);
            wA = q1.y * __expf(eA);
        }
        if (mB) {
            float dyB = syB - q0.y;
            float eB  = -(q0.z*(dx*dx + vx) + q0.w*(dx*dyB) + q1.x*(dyB*dyB + vyB));
            eB = fminf(fmaxf(eB, -20.0f), 0.0f);
            wB = q1.y * __expf(eB);
        }
        SA += wA; mxA = fmaxf(mxA, wA); mnA = fminf(mnA, wA);
        SB += wB; mxB = fmaxf(mxB, wB); mnB = fminf(mnB, wB);
    }

    // culled / warp-skipped gaussians contribute exactly zero to min/max/sum
    if (skipped || (nfull + (NG - pstart) < NG)) {
        mnA = fminf(mnA, 0.0f); mxA = fmaxf(mxA, 0.0f);
        mnB = fminf(mnB, 0.0f); mxB = fmaxf(mxB, 0.0f);
    }

    float dmA = 0.5f*(SA - 512.0f*mnA)/((mxA - mnA) + 1e-6f) + SA/(SA + 1e-6f);
    float dmB = 0.5f*(SB - 512.0f*mnB)/((mxB - mnB) + 1e-6f) + SB/(SB + 1e-6f);
    g_d[v*VPIX + fyA*IMGW + fx] = dmA;
    g_d[v*VPIX + fyB*IMGW + fx] = dmB;
}

// ---------------------------------------------------------------------------
// Fully fused fill (BOTH steps) + stats. Each block owns an 8-row output slab;
// loads a 20-row halo of the read-only g_d, computes step-0 blur+merge on 14
// rows locally (OOB rows zeroed = conv zero-padding), then step-1 on its 8
// rows. Writes g_t and accumulates global sum/sumsq.
// ---------------------------------------------------------------------------
__device__ __forceinline__ void blur_weights(float& K0, float& K1, float& K2, float& K3)
{
    const double E1 = 0.60653065971263342;   // exp(-0.5)
    const double E2 = 0.13533528323661270;   // exp(-2.0)
    const double E3 = 0.011108996538242306;  // exp(-4.5)
    const double KS = 1.0 + 2.0*(E1 + E2 + E3);
    K0 = (float)(1.0/KS); K1 = (float)(E1/KS); K2 = (float)(E2/KS); K3 = (float)(E3/KS);
}

__global__ __launch_bounds__(256) void fill2_kernel()
{
    const int v  = blockIdx.y;
    const int r0 = blockIdx.x * 8;
    const int t  = threadIdx.x;

    float K0,K1,K2,K3; blur_weights(K0,K1,K2,K3);

    __shared__ float sA[20 * 224];   // original d, rows r0-6 .. r0+13
    __shared__ float sB[14 * 224];   // vblur scratch (step0: 14 rows, step1: 8)
    __shared__ float sC[14 * 224];   // step-0 merged d, rows r0-3 .. r0+10

    for (int idx = t; idx < 20*224; idx += 256) {
        int row = idx / 224;
        int x   = idx - row * 224;
        int y   = r0 - 6 + row;
        sA[idx] = (y >= 0 && y < 224) ? g_d[v*VPIX + y*224 + x] : 0.0f;
    }
    __syncthreads();

    // step-0 vertical blur on 14 rows (abs rows r0-3 .. r0+10)
    for (int idx = t; idx < 14*224; idx += 256) {
        sB[idx] = K0 *  sA[idx + 3*224]
                + K1 * (sA[idx + 2*224] + sA[idx + 4*224])
                + K2 * (sA[idx + 1*224] + sA[idx + 5*224])
                + K3 * (sA[idx]          + sA[idx + 6*224]);
    }
    __syncthreads();

    // step-0 horizontal blur + merge -> sC (zero OOB rows: conv zero-padding)
    for (int idx = t; idx < 14*224; idx += 256) {
        int j = idx / 224;
        int x = idx - j * 224;
        int yabs = r0 - 3 + j;
        float acc = K0 * sB[idx];
        if (x >= 1)   acc += K1 * sB[idx - 1];
        if (x >= 2)   acc += K2 * sB[idx - 2];
        if (x >= 3)   acc += K3 * sB[idx - 3];
        if (x <= 222) acc += K1 * sB[idx + 1];
        if (x <= 221) acc += K2 * sB[idx + 2];
        if (x <= 220) acc += K3 * sB[idx + 3];
        float dv = sA[idx + 3*224];
        float res = (dv > 1e-6f) ? dv : acc;
        sC[idx] = (yabs >= 0 && yabs < 224) ? res : 0.0f;
    }
    __syncthreads();

    // step-1 vertical blur on the 8 output rows
    for (int idx = t; idx < 8*224; idx += 256) {
        sB[idx] = K0 *  sC[idx + 3*224]
                + K1 * (sC[idx + 2*224] + sC[idx + 4*224])
                + K2 * (sC[idx + 1*224] + sC[idx + 5*224])
                + K3 * (sC[idx]          + sC[idx + 6*224]);
    }
    __syncthreads();

    // step-1 horizontal blur + merge + store + stats
    double s1 = 0.0, s2 = 0.0;
    for (int idx = t; idx < 8*224; idx += 256) {
        int j = idx / 224;
        int x = idx - j * 224;
        float acc = K0 * sB[idx];
        if (x >= 1)   acc += K1 * sB[idx - 1];
        if (x >= 2)   acc += K2 * sB[idx - 2];
        if (x >= 3)   acc += K3 * sB[idx - 3];
        if (x <= 222) acc += K1 * sB[idx + 1];
        if (x <= 221) acc += K2 * sB[idx + 2];
        if (x <= 220) acc += K3 * sB[idx + 3];
        float dv  = sC[idx + 3*224];
        float res = (dv > 1e-6f) ? dv : acc;
        g_t[v*VPIX + (r0 + j)*224 + x] = res;
        s1 += (double)res; s2 += (double)res * (double)res;
    }

    #pragma unroll
    for (int o = 16; o > 0; o >>= 1) {
        s1 += __shfl_down_sync(0xffffffffu, s1, o);
        s2 += __shfl_down_sync(0xffffffffu, s2, o);
    }
    __shared__ double ws[8], ws2[8];
    int lane = t & 31, wid = t >> 5;
    if (lane == 0) { ws[wid] = s1; ws2[wid] = s2; }
    __syncthreads();
    if (t == 0) {
        double a = 0.0, b = 0.0;
        for (int w = 0; w < 8; w++) { a += ws[w]; b += ws2[w]; }
        atomicAdd(&g_acc[0], a);
        atomicAdd(&g_acc[1], b);
    }
}

// ---------------------------------------------------------------------------
// Global mean / std(ddof=1) normalize
// ---------------------------------------------------------------------------
__global__ __launch_bounds__(256) void norm_kernel(float* __restrict__ out)
{
    int i = blockIdx.x*256 + threadIdx.x;
    if (i >= NPIX) return;
    double s1 = g_acc[0], s2 = g_acc[1];
    double mean = s1 / (double)NPIX;
    double var  = (s2 - s1*mean) / (double)(NPIX - 1);
    float stdf  = (float)sqrt(fmax(var, 0.0));
    out[i] = (g_t[i] - (float)mean) / (stdf + 1e-6f);
}

// ---------------------------------------------------------------------------
extern "C" void kernel_launch(void* const* d_in, const int* in_sizes, int n_in,
                              void* d_out, int out_size)
{
    const float* pos = (const float*)d_in[0];  // (1,512,3)
    const float* cov = (const float*)d_in[1];  // (1,512,3,3)
    const float* opa = (const float*)d_in[2];  // (1,512)
    const float* imp = (const float*)d_in[3];  // (1,1000)

    prep_kernel<<<48, 32>>>(pos, cov, opa, imp);
    splat_kernel<<<dim3(14, 14, 3), 128>>>();
    fill2_kernel<<<dim3(28, 3), 256>>>();
    norm_kernel<<<(NPIX + 255)/256, 256>>>((float*)d_out);
}

// round 11
// speedup vs baseline: 1.2940x; 1.2940x over previous
#include <cuda_runtime.h>
#include <math.h>

#define NG   512
#define IMGW 224
#define VPIX (IMGW*IMGW)
#define NPIX (3*VPIX)

#define L2E   1.4426950408889634f
#define UMIN  (-28.853900817779268f)       // -20 * log2(e)
#define EKF   2.061153622438558e-9f        // exp(-20) == exp2(UMIN)

// Scratch (no cudaMalloc allowed)
__device__ float  g_par[3*NG*8];   // px,py,A,B,C,w0,F0,rsat2  (A=-a*l2e etc.)
__device__ float  g_d[NPIX];       // splat output
__device__ float  g_t[NPIX];       // fill output (pre-norm)
__device__ double g_acc[2];        // sum, sumsq

__device__ __forceinline__ float ex2f(float x)
{
    float y;
    asm("ex2.approx.f32 %0, %1;" : "=f"(y) : "f"(x));
    return y;
}

// ---------------------------------------------------------------------------
// prep: 48 blocks x 32 threads, thread -> (view, gaussian). Warp-redundant
// position bounds; iterated f32 cov chain (v+1 times); f64 3x3 inverse;
// log2e-folded screen-space quadratic coefficients + saturation radius.
// ---------------------------------------------------------------------------
__global__ __launch_bounds__(32) void prep_kernel(const float* __restrict__ pos,
                                                  const float* __restrict__ cov,
                                                  const float* __restrict__ opa,
                                                  const float* __restrict__ imp)
{
    const int lane = threadIdx.x;
    const int bx   = blockIdx.x;          // [0,48)
    const int v    = bx >> 4;
    const int n    = (bx & 15) * 32 + lane;

    if (bx == 0 && lane == 0) { g_acc[0] = 0.0; g_acc[1] = 0.0; }

    // global min/max of each coordinate (warp-redundant)
    float mn0 =  1e30f, mn1 =  1e30f, mn2 =  1e30f;
    float mx0 = -1e30f, mx1 = -1e30f, mx2 = -1e30f;
    for (int g = lane; g < NG; g += 32) {
        float p0 = pos[g*3+0], p1 = pos[g*3+1], p2 = pos[g*3+2];
        mn0 = fminf(mn0, p0); mx0 = fmaxf(mx0, p0);
        mn1 = fminf(mn1, p1); mx1 = fmaxf(mx1, p1);
        mn2 = fminf(mn2, p2); mx2 = fmaxf(mx2, p2);
    }
    #pragma unroll
    for (int o = 16; o > 0; o >>= 1) {
        mn0 = fminf(mn0, __shfl_xor_sync(0xffffffffu, mn0, o));
        mx0 = fmaxf(mx0, __shfl_xor_sync(0xffffffffu, mx0, o));
        mn1 = fminf(mn1, __shfl_xor_sync(0xffffffffu, mn1, o));
        mx1 = fmaxf(mx1, __shfl_xor_sync(0xffffffffu, mx1, o));
        mn2 = fminf(mn2, __shfl_xor_sync(0xffffffffu, mn2, o));
        mx2 = fmaxf(mx2, __shfl_xor_sync(0xffffffffu, mx2, o));
    }
    float bmn[3] = { mn0, mn1, mn2 };
    float bmx[3] = { mx0, mx1, mx2 };

    // cov chain applied (v+1) times (fp32, matching reference ops/order)
    float C00 = cov[n*9+0], C01 = cov[n*9+1], C02 = cov[n*9+2];
    float C10 = cov[n*9+3], C11 = cov[n*9+4], C12 = cov[n*9+5];
    float C20 = cov[n*9+6], C21 = cov[n*9+7], C22 = cov[n*9+8];
    for (int it = 0; it <= v; it++) {
        float t;
        t = 0.5f*(C01 + C10); C01 = t; C10 = t;
        t = 0.5f*(C02 + C20); C02 = t; C20 = t;
        t = 0.5f*(C12 + C21); C12 = t; C21 = t;
        C00 += 1e-6f; C11 += 1e-6f; C22 += 1e-6f;
        float nrm = sqrtf(C00*C00 + C01*C01 + C02*C02 +
                          C10*C10 + C11*C11 + C12*C12 +
                          C20*C20 + C21*C21 + C22*C22);
        float den = nrm + 1e-6f;
        C00 /= den; C01 /= den; C02 /= den;
        C10 /= den; C11 /= den; C12 /= den;
        C20 /= den; C21 /= den; C22 /= den;
    }

    // f64 symmetric 3x3 inverse
    double d00 = C00, d01 = C01, d02 = C02, d11 = C11, d12 = C12, d22 = C22;
    double m00 = d11*d22 - d12*d12;
    double m01 = d02*d12 - d01*d22;
    double m02 = d01*d12 - d02*d11;
    double m11 = d00*d22 - d02*d02;
    double m12 = d01*d02 - d00*d12;
    double m22 = d00*d11 - d01*d01;
    double det = d00*m00 + d01*m01 + d02*m02;
    double idet = 1.0 / det;

    const int A0[3] = {0, 0, 2};
    const int A1[3] = {1, 2, 1};
    const int a0 = A0[v], a1 = A1[v];
    double cof[3][3] = {{m00,m01,m02},{m01,m11,m12},{m02,m12,m22}};
    float a  = (float)(cof[a0][a0]*idet) + 1e-10f;
    float b2 = 2.0f * (float)(cof[a0][a1]*idet);
    float c  = (float)(cof[a1][a1]*idet) + 1e-10f;

    // affine map to [0,111] screen coords (replicating reference fp ops)
    float mnx = bmn[a0], mxx = bmx[a0];
    float mny = bmn[a1], mxy = bmx[a1];
    float rx  = (mxx - mnx) + 1e-6f;
    float m2x = mnx - 0.5f*rx;
    float x2x = mxx + 0.5f*rx;
    float r2x = (x2x - m2x) + 1e-6f;
    float ry  = (mxy - mny) + 1e-6f;
    float m2y = mny - 0.5f*ry;
    float x2y = mxy + 0.5f*ry;
    float r2y = (x2y - m2y) + 1e-6f;
    float Pa  = pos[n*3 + a0];
    float Pb  = pos[n*3 + a1];
    float px = fminf(fmaxf((Pa - m2x) / r2x * 111.0f, 0.0f), 111.0f);
    float py = fminf(fmaxf((Pb - m2y) / r2y * 111.0f, 0.0f), 111.0f);

    float w0 = opa[n] * fminf(fmaxf(imp[n], 0.5f), 2.0f);

    // log2e-folded (negated) coefficients
    float Af = -L2E * a;
    float Bf = -L2E * b2;
    float Cf = -L2E * c;
    float F0 = 0.1875f * (Af + Cf);

    // saturation radius: quad >= lam * d^2, quad >= 20 => exactly clipped
    float bh  = 0.5f * b2;
    float lam = 0.5f*(a + c) - sqrtf(0.25f*(a - c)*(a - c) + bh*bh);
    float rsat2;
    if (lam > 1e-8f) {
        float rs = sqrtf(20.0f / lam) + 0.3536f;   // +0.25*sqrt(2) s-coord margin
        rsat2 = rs * rs;
    } else {
        rsat2 = 3.0e38f;                            // indefinite: never saturated
    }

    float* dst = &g_par[(v*NG + n)*8];
    dst[0] = px; dst[1] = py; dst[2] = Af; dst[3] = Bf;
    dst[4] = Cf; dst[5] = w0; dst[6] = F0; dst[7] = rsat2;
}

// ---------------------------------------------------------------------------
// Exact-eval inner loop (templated on EDGE pixel handling and disc MASK test).
// ---------------------------------------------------------------------------
template<bool EDGE, bool MASKED>
__device__ __forceinline__ void eval_list(
    const float* __restrict__ sp, int i0, int i1,
    float sx, float vx, float syA, float vyA, float syB, float vyB,
    float hx, float hyA, float hyB,
    float& SA, float& mxA, float& mnA,
    float& SB, float& mxB, float& mnB, bool& skipped)
{
    #pragma unroll 2
    for (int i = i0; i < i1; i++) {
        float4 q0 = *(const float4*)(sp + i*8);      // px,py,A,B
        float4 q1 = *(const float4*)(sp + i*8 + 4);  // C,w0,F0,rsat2
        bool mA = true, mB = true;
        if (MASKED) {
            float dxh  = hx - q0.x;
            float dxh2 = dxh * dxh;
            float dyhA = hyA - q0.y;
            float dyhB = hyB - q0.y;
            mA = dyhA*dyhA + dxh2 < 400.0f;
            mB = dyhB*dyhB + dxh2 < 400.0f;
            if (!__any_sync(0xffffffffu, mA | mB)) { skipped = true; continue; }
        }
        float dx  = sx - q0.x;
        float bdx = q0.w * dx;
        float base;
        if (EDGE) base = q0.z * fmaf(dx, dx, vx);
        else      base = fmaf(q0.z, dx*dx, q1.z);
        {
            float dy = syA - q0.y;
            float u;
            if (EDGE) u = fmaf(q1.x, fmaf(dy, dy, vyA), fmaf(bdx, dy, base));
            else      u = fmaf(q1.x, dy*dy, fmaf(bdx, dy, base));
            u = fmaxf(fminf(u, 0.0f), UMIN);
            float w = mA ? q1.y * ex2f(u) : 0.0f;
            SA += w; mxA = fmaxf(mxA, w); mnA = fminf(mnA, w);
        }
        {
            float dy = syB - q0.y;
            float u;
            if (EDGE) u = fmaf(q1.x, fmaf(dy, dy, vyB), fmaf(bdx, dy, base));
            else      u = fmaf(q1.x, dy*dy, fmaf(bdx, dy, base));
            u = fmaxf(fminf(u, 0.0f), UMIN);
            float w = mB ? q1.y * ex2f(u) : 0.0f;
            SB += w; mxB = fmaxf(mxB, w); mnB = fminf(mnB, w);
        }
    }
}

// ---------------------------------------------------------------------------
// Splat: 16x16 pixel tile, 128 threads, 2 pixels/thread (rows y, y+8).
// Compaction classifies each gaussian per tile:
//   fullA: exact eval, no mask          (not saturated, fully inside disc)
//   partA: exact eval with disc mask    (not saturated, disc boundary)
//   B:     saturated + fully in disc -> per-tile scalars (zero loop cost)
//   C:     saturated + disc boundary -> per-pixel disc test only
//   culled: outside disc everywhere  -> exact zero (min/max fold)
// Saturated contribution is EXACT: clip makes w = w0*exp(-20) bit-identically.
// ---------------------------------------------------------------------------
__global__ __launch_bounds__(128) void splat_kernel()
{
    const int v    = blockIdx.y;
    const int tile = (blockIdx.x * 15) % 196;    // wave-balance permutation
    const int fx0  = (tile % 14) * 16, fy0 = (tile / 14) * 16;
    const int t    = threadIdx.x;
    const int lane = t & 31, wid = t >> 5;
    const int fx   = fx0 + (t & 15);
    const int fyA  = fy0 + (t >> 4);
    const int fyB  = fyA + 8;

    float sx, vx;
    if (fx == 0)        { sx = 0.0f;   vx = 0.0f; }
    else if (fx == 223) { sx = 111.0f; vx = 0.0f; }
    else                { sx = (float)fx * 0.5f - 0.25f; vx = 0.1875f; }
    float syA, vyA;
    if (fyA == 0)        { syA = 0.0f;   vyA = 0.0f; }
    else                 { syA = (float)fyA * 0.5f - 0.25f; vyA = 0.1875f; }
    float syB, vyB;
    if (fyB == 223)      { syB = 111.0f; vyB = 0.0f; }
    else                 { syB = (float)fyB * 0.5f - 0.25f; vyB = 0.1875f; }

    const float hx  = (float)(fx  >> 1);
    const float hyA = (float)(fyA >> 1);
    const float hyB = (float)(fyB >> 1);

    const float rx0 = (float)(fx0 >> 1), rx1 = (float)((fx0 + 15) >> 1);
    const float ry0 = (float)(fy0 >> 1), ry1 = (float)((fy0 + 15) >> 1);

    __shared__ float spA[NG * 8];
    __shared__ float spC[NG * 4];
    __shared__ int   cFA[4], cPA[4], cC[4], cB[4];
    __shared__ float rSum[4], rMin[4], rMax[4];
    __shared__ int   s_front, s_back, s_c, s_nB;
    __shared__ float s_sumB, s_minB, s_maxB;
    if (t == 0) {
        s_front = 0; s_back = NG; s_c = 0; s_nB = 0;
        s_sumB = 0.0f; s_minB = 1e30f; s_maxB = -1e30f;
    }
    __syncthreads();

    const float* par = g_par + v * NG * 8;
    const unsigned ltm = (1u << lane) - 1u;

    for (int base = 0; base < NG; base += 128) {
        const int n = base + t;
        float4 q0 = *(const float4*)(par + n*8);
        float4 q1 = *(const float4*)(par + n*8 + 4);
        float px = q0.x, py = q0.y;
        float nx = fminf(fmaxf(px, rx0), rx1) - px;
        float ny = fminf(fmaxf(py, ry0), ry1) - py;
        float dnear2 = nx*nx + ny*ny;
        float fxd = fmaxf(px - rx0, rx1 - px);
        float fyd = fmaxf(py - ry0, ry1 - py);
        float dfar2 = fxd*fxd + fyd*fyd;

        bool keep   = dnear2 < 400.0f;
        bool inside = dfar2  < 400.0f;
        bool sat    = keep && (dnear2 >= q1.w);
        bool bBall  = sat && inside;
        bool bCc    = sat && !inside;
        bool bFA    = keep && !sat && inside;
        bool bPA    = keep && !sat && !inside;

        unsigned mFA = __ballot_sync(0xffffffffu, bFA);
        unsigned mPA = __ballot_sync(0xffffffffu, bPA);
        unsigned mCc = __ballot_sync(0xffffffffu, bCc);
        unsigned mBB = __ballot_sync(0xffffffffu, bBall);

        // warp-reduce B scalars
        float sv  = bBall ? q1.y : 0.0f;
        float mnv = bBall ? q1.y : 1e30f;
        float mxv = bBall ? q1.y : -1e30f;
        #pragma unroll
        for (int o = 16; o > 0; o >>= 1) {
            sv  += __shfl_xor_sync(0xffffffffu, sv,  o);
            mnv  = fminf(mnv, __shfl_xor_sync(0xffffffffu, mnv, o));
            mxv  = fmaxf(mxv, __shfl_xor_sync(0xffffffffu, mxv, o));
        }
        if (lane == 0) {
            cFA[wid] = __popc(mFA); cPA[wid] = __popc(mPA);
            cC[wid]  = __popc(mCc); cB[wid]  = __popc(mBB);
            rSum[wid] = sv; rMin[wid] = mnv; rMax[wid] = mxv;
        }
        __syncthreads();

        int offF = s_front, offP = 0, offC = s_c;
        int totF = 0, totP = 0;
        #pragma unroll
        for (int w = 0; w < 4; w++) {
            if (w < wid) { offF += cFA[w]; offP += cPA[w]; offC += cC[w]; }
            totF += cFA[w]; totP += cPA[w];
        }
        int basePslot = s_back - totP;
        if (bFA | bPA) {
            int slot = bFA ? (offF + __popc(mFA & ltm))
                           : (basePslot + offP + __popc(mPA & ltm));
            *(float4*)(spA + slot*8)     = q0;
            *(float4*)(spA + slot*8 + 4) = q1;
        }
        if (bCc) {
            int slot = offC + __popc(mCc & ltm);
            *(float4*)(spC + slot*4) = make_float4(px, py, EKF * q1.y, 0.0f);
        }
        __syncthreads();
        if (t == 0) {
            int tF = 0, tP = 0, tC = 0, tB = 0;
            float aS = 0.0f, aMn = 1e30f, aMx = -1e30f;
            #pragma unroll
            for (int w = 0; w < 4; w++) {
                tF += cFA[w]; tP += cPA[w]; tC += cC[w]; tB += cB[w];
                aS += rSum[w]; aMn = fminf(aMn, rMin[w]); aMx = fmaxf(aMx, rMax[w]);
            }
            s_front += tF; s_back -= tP; s_c += tC; s_nB += tB;
            s_sumB += aS;
            s_minB = fminf(s_minB, aMn);
            s_maxB = fmaxf(s_maxB, aMx);
        }
        __syncthreads();
    }
    const int nfull = s_front, pstart = s_back, nC = s_c, nB = s_nB;
    const float sumB = s_sumB, minB = s_minB, maxB = s_maxB;

    float SA = 0.0f, mxA = -1e30f, mnA = 1e30f;
    float SB = 0.0f, mxB = -1e30f, mnB = 1e30f;
    bool skipped = false;

    const bool interior = (fx0 != 0) && (fx0 != 208) && (fy0 != 0) && (fy0 != 208);
    if (interior) {
        eval_list<false,false>(spA, 0, nfull, sx, vx, syA, vyA, syB, vyB,
                               hx, hyA, hyB, SA, mxA, mnA, SB, mxB, mnB, skipped);
        eval_list<false,true >(spA, pstart, NG, sx, vx, syA, vyA, syB, vyB,
                               hx, hyA, hyB, SA, mxA, mnA, SB, mxB, mnB, skipped);
    } else {
        eval_list<true,false>(spA, 0, nfull, sx, vx, syA, vyA, syB, vyB,
                              hx, hyA, hyB, SA, mxA, mnA, SB, mxB, mnB, skipped);
        eval_list<true,true >(spA, pstart, NG, sx, vx, syA, vyA, syB, vyB,
                              hx, hyA, hyB, SA, mxA, mnA, SB, mxB, mnB, skipped);
    }

    // C list: saturated, disc-boundary -> per-pixel disc test only
    #pragma unroll 2
    for (int i = 0; i < nC; i++) {
        float4 q = *(const float4*)(spC + i*4);   // px,py,EK*w0
        float dxh  = hx - q.x;
        float dxh2 = dxh * dxh;
        float dyhA = hyA - q.y;
        float dyhB = hyB - q.y;
        float wA = (dyhA*dyhA + dxh2 < 400.0f) ? q.z : 0.0f;
        float wB = (dyhB*dyhB + dxh2 < 400.0f) ? q.z : 0.0f;
        SA += wA; mxA = fmaxf(mxA, wA); mnA = fminf(mnA, wA);
        SB += wB; mxB = fmaxf(mxB, wB); mnB = fminf(mnB, wB);
    }

    // B scalars: identical contribution to every tile pixel
    if (nB > 0) {
        float add = EKF * sumB;
        SA += add; SB += add;
        float bmnv = EKF * minB, bmxv = EKF * maxB;
        mnA = fminf(mnA, bmnv); mxA = fmaxf(mxA, bmxv);
        mnB = fminf(mnB, bmnv); mxB = fmaxf(mxB, bmxv);
    }

    // culled / skipped gaussians contribute exactly zero
    int listed = nfull + (NG - pstart) + nC + nB;
    if (skipped || listed < NG) {
        mnA = fminf(mnA, 0.0f); mxA = fmaxf(mxA, 0.0f);
        mnB = fminf(mnB, 0.0f); mxB = fmaxf(mxB, 0.0f);
    }

    float dmA = 0.5f*(SA - 512.0f*mnA)/((mxA - mnA) + 1e-6f) + SA/(SA + 1e-6f);
    float dmB = 0.5f*(SB - 512.0f*mnB)/((mxB - mnB) + 1e-6f) + SB/(SB + 1e-6f);
    g_d[v*VPIX + fyA*IMGW + fx] = dmA;
    g_d[v*VPIX + fyB*IMGW + fx] = dmB;
}

// ---------------------------------------------------------------------------
// Fully fused fill (both steps) + stats (unchanged from R10).
// ---------------------------------------------------------------------------
__device__ __forceinline__ void blur_weights(float& K0, float& K1, float& K2, float& K3)
{
    const double E1 = 0.60653065971263342;
    const double E2 = 0.13533528323661270;
    const double E3 = 0.011108996538242306;
    const double KS = 1.0 + 2.0*(E1 + E2 + E3);
    K0 = (float)(1.0/KS); K1 = (float)(E1/KS); K2 = (float)(E2/KS); K3 = (float)(E3/KS);
}

__global__ __launch_bounds__(256) void fill2_kernel()
{
    const int v  = blockIdx.y;
    const int r0 = blockIdx.x * 8;
    const int t  = threadIdx.x;

    float K0,K1,K2,K3; blur_weights(K0,K1,K2,K3);

    __shared__ float sA[20 * 224];
    __shared__ float sB[14 * 224];
    __shared__ float sC[14 * 224];

    for (int idx = t; idx < 20*224; idx += 256) {
        int row = idx / 224;
        int x   = idx - row * 224;
        int y   = r0 - 6 + row;
        sA[idx] = (y >= 0 && y < 224) ? g_d[v*VPIX + y*224 + x] : 0.0f;
    }
    __syncthreads();

    for (int idx = t; idx < 14*224; idx += 256) {
        sB[idx] = K0 *  sA[idx + 3*224]
                + K1 * (sA[idx + 2*224] + sA[idx + 4*224])
                + K2 * (sA[idx + 1*224] + sA[idx + 5*224])
                + K3 * (sA[idx]          + sA[idx + 6*224]);
    }
    __syncthreads();

    for (int idx = t; idx < 14*224; idx += 256) {
        int j = idx / 224;
        int x = idx - j * 224;
        int yabs = r0 - 3 + j;
        float acc = K0 * sB[idx];
        if (x >= 1)   acc += K1 * sB[idx - 1];
        if (x >= 2)   acc += K2 * sB[idx - 2];
        if (x >= 3)   acc += K3 * sB[idx - 3];
        if (x <= 222) acc += K1 * sB[idx + 1];
        if (x <= 221) acc += K2 * sB[idx + 2];
        if (x <= 220) acc += K3 * sB[idx + 3];
        float dv = sA[idx + 3*224];
        float res = (dv > 1e-6f) ? dv : acc;
        sC[idx] = (yabs >= 0 && yabs < 224) ? res : 0.0f;
    }
    __syncthreads();

    for (int idx = t; idx < 8*224; idx += 256) {
        sB[idx] = K0 *  sC[idx + 3*224]
                + K1 * (sC[idx + 2*224] + sC[idx + 4*224])
                + K2 * (sC[idx + 1*224] + sC[idx + 5*224])
                + K3 * (sC[idx]          + sC[idx + 6*224]);
    }
    __syncthreads();

    double s1 = 0.0, s2 = 0.0;
    for (int idx = t; idx < 8*224; idx += 256) {
        int j = idx / 224;
        int x = idx - j * 224;
        float acc = K0 * sB[idx];
        if (x >= 1)   acc += K1 * sB[idx - 1];
        if (x >= 2)   acc += K2 * sB[idx - 2];
        if (x >= 3)   acc += K3 * sB[idx - 3];
        if (x <= 222) acc += K1 * sB[idx + 1];
        if (x <= 221) acc += K2 * sB[idx + 2];
        if (x <= 220) acc += K3 * sB[idx + 3];
        float dv  = sC[idx + 3*224];
        float res = (dv > 1e-6f) ? dv : acc;
        g_t[v*VPIX + (r0 + j)*224 + x] = res;
        s1 += (double)res; s2 += (double)res * (double)res;
    }

    #pragma unroll
    for (int o = 16; o > 0; o >>= 1) {
        s1 += __shfl_down_sync(0xffffffffu, s1, o);
        s2 += __shfl_down_sync(0xffffffffu, s2, o);
    }
    __shared__ double ws[8], ws2[8];
    int lane = t & 31, wid = t >> 5;
    if (lane == 0) { ws[wid] = s1; ws2[wid] = s2; }
    __syncthreads();
    if (t == 0) {
        double a = 0.0, b = 0.0;
        for (int w = 0; w < 8; w++) { a += ws[w]; b += ws2[w]; }
        atomicAdd(&g_acc[0], a);
        atomicAdd(&g_acc[1], b);
    }
}

// ---------------------------------------------------------------------------
// Normalize: f64 mean/std computed ONCE per block, f32 stream for the rest.
// ---------------------------------------------------------------------------
__global__ __launch_bounds__(256) void norm_kernel(float* __restrict__ out)
{
    __shared__ float sBias, sScale;
    if (threadIdx.x == 0) {
        double s1 = g_acc[0], s2 = g_acc[1];
        double mean = s1 / (double)NPIX;
        double var  = (s2 - s1*mean) / (double)(NPIX - 1);
        double stdd = sqrt(fmax(var, 0.0));
        sBias  = (float)mean;
        sScale = (float)(1.0 / (stdd + 1e-6));
    }
    __syncthreads();
    int i = blockIdx.x*256 + threadIdx.x;
    if (i >= NPIX) return;
    out[i] = (g_t[i] - sBias) * sScale;
}

// ---------------------------------------------------------------------------
extern "C" void kernel_launch(void* const* d_in, const int* in_sizes, int n_in,
                              void* d_out, int out_size)
{
    const float* pos = (const float*)d_in[0];  // (1,512,3)
    const float* cov = (const float*)d_in[1];  // (1,512,3,3)
    const float* opa = (const float*)d_in[2];  // (1,512)
    const float* imp = (const float*)d_in[3];  // (1,1000)

    prep_kernel<<<48, 32>>>(pos, cov, opa, imp);
    splat_kernel<<<dim3(196, 3), 128>>>();
    fill2_kernel<<<dim3(28, 3), 256>>>();
    norm_kernel<<<(NPIX + 255)/256, 256>>>((float*)d_out);
}